// round 10
// baseline (speedup 1.0000x reference)
#include <cuda_runtime.h>
#include <cuda_fp16.h>
#include <math.h>
#include <stdint.h>

#define NE    8
#define HDIM  1024
#define IDIM  4096
#define NTOK  4096
#define CAP   4096
#define NASSIGN (NTOK * 2)
#define NX1   64        // GEMM1 x-items per (e,mt): IDIM/64 logical cols
#define NX2   16        // GEMM2 x-items per (e,mt): HDIM/64 cols
#define NCTA  304       // 152 SMs * 2 CTAs

// ---------------- scratch (static device globals) ----------------------------
__device__ __half g_Xg[NE * CAP * HDIM];   // gathered activations fp16
__device__ __half g_H [NE * CAP * IDIM];   // silu(X@w1)*(X@w3) fp16
__device__ int   g_cnt[NE];
__device__ int   g_next;
__device__ int   g_nitems;
__device__ int   g_done[NE * 32];          // per (e,mt): completed GEMM1 x-items
__device__ int   g_items[32768];           // encoded work items
__device__ int   g_slotOf[NASSIGN];        // assignment -> slot
__device__ int   g_tok[NE * CAP];          // slot -> token
__device__ float g_w [NE * CAP];           // slot -> combine weight

// ---------------- helpers -----------------------------------------------------
__device__ __forceinline__ unsigned smem_u32(const void* p) {
    return (unsigned)__cvta_generic_to_shared(p);
}
#define CPA16(dst, src) asm volatile("cp.async.cg.shared.global [%0], [%1], 16;" :: "r"(dst), "l"(src))
#define CP_COMMIT()     asm volatile("cp.async.commit_group;")

#define LDSM4(R, addr) \
    asm volatile("ldmatrix.sync.aligned.m8n8.x4.shared.b16 {%0,%1,%2,%3}, [%4];" \
        : "=r"((R)[0]), "=r"((R)[1]), "=r"((R)[2]), "=r"((R)[3]) : "r"(addr))
#define LDSM4T(r0, r1, r2, r3, addr) \
    asm volatile("ldmatrix.sync.aligned.m8n8.x4.trans.shared.b16 {%0,%1,%2,%3}, [%4];" \
        : "=r"(r0), "=r"(r1), "=r"(r2), "=r"(r3) : "r"(addr))
#define MMA16816(acc, a, b) \
    asm volatile("mma.sync.aligned.m16n8k16.row.col.f32.f16.f16.f32 " \
        "{%0,%1,%2,%3}, {%4,%5,%6,%7}, {%8,%9}, {%0,%1,%2,%3};" \
        : "+f"((acc)[0]), "+f"((acc)[1]), "+f"((acc)[2]), "+f"((acc)[3]) \
        : "r"((a)[0]), "r"((a)[1]), "r"((a)[2]), "r"((a)[3]), "r"((b)[0]), "r"((b)[1]))

// ---------------- kernel 0: zero counters ------------------------------------
__global__ void zero_kernel() {
    int tid = threadIdx.x;
    if (tid < NE) g_cnt[tid] = 0;
    if (tid == 8) g_next = 0;
    g_done[tid] = 0;   // 256 entries
}

// ---------------- kernel 1: router + scatter + out-row zero ------------------
__global__ void router_kernel(const float* __restrict__ X,
                              const float* __restrict__ GW,
                              float* __restrict__ out,
                              float* __restrict__ out_logits) {
    int t = blockIdx.x;
    int w = threadIdx.x >> 5;
    int lane = threadIdx.x & 31;
    __shared__ float slog[NE];

    const float* x = X + (size_t)t * HDIM;
    float acc = 0.f;
    for (int i = lane; i < HDIM; i += 32)
        acc += x[i] * GW[i * NE + w];
    #pragma unroll
    for (int o = 16; o > 0; o >>= 1)
        acc += __shfl_xor_sync(0xffffffffu, acc, o);
    if (lane == 0) {
        slog[w] = acc;
        out_logits[t * NE + w] = acc;
    }

    // zero this token's output row (poisoned 0xAA by harness)
    float4 z = make_float4(0.f, 0.f, 0.f, 0.f);
    ((float4*)(out + (size_t)t * HDIM))[threadIdx.x] = z;

    __syncthreads();
    if (threadIdx.x == 0) {
        int i0 = 0; float l0 = slog[0];
        #pragma unroll
        for (int e = 1; e < NE; e++)
            if (slog[e] > l0) { l0 = slog[e]; i0 = e; }
        int i1 = -1; float l1 = -1e30f;
        #pragma unroll
        for (int e = 0; e < NE; e++)
            if (e != i0 && slog[e] > l1) { l1 = slog[e]; i1 = e; }
        float e1 = expf(l1 - l0);
        float inv = 1.f / (1.f + e1);
        int p0 = atomicAdd(&g_cnt[i0], 1);
        int s0 = i0 * CAP + p0;
        g_slotOf[2 * t] = s0; g_tok[s0] = t; g_w[s0] = inv;
        int p1 = atomicAdd(&g_cnt[i1], 1);
        int s1 = i1 * CAP + p1;
        g_slotOf[2 * t + 1] = s1; g_tok[s1] = t; g_w[s1] = e1 * inv;
    }
}

// ---------------- kernel 2: gather + fp16 convert ----------------------------
__global__ void gather_kernel(const float* __restrict__ X) {
    int a = blockIdx.x;
    int slot = g_slotOf[a];
    int t = a >> 1;
    const float4* src = (const float4*)(X + (size_t)t * HDIM);
    __half2* dst = (__half2*)(g_Xg + (size_t)slot * HDIM);
    int i = threadIdx.x;
    float4 v = src[i];
    dst[2 * i]     = __floats2half2_rn(v.x, v.y);
    dst[2 * i + 1] = __floats2half2_rn(v.z, v.w);
}

// ---------------- kernel 3: build work-item queue ----------------------------
// item: bit14 = phase, bits13-11 = e, bits10-6 = mt, bits5-0 = x
__global__ void build_items_kernel() {
    __shared__ int nt[NE], b1[NE], b2[NE];
    int tid = threadIdx.x;
    if (tid == 0) {
        int off = 0;
        #pragma unroll
        for (int e = 0; e < NE; e++) nt[e] = (g_cnt[e] + 127) >> 7;
        #pragma unroll
        for (int e = 0; e < NE; e++) { b1[e] = off; off += nt[e] * NX1; }
        #pragma unroll
        for (int e = 0; e < NE; e++) { b2[e] = off; off += nt[e] * NX2; }
        g_nitems = off;
    }
    __syncthreads();
    for (int e = 0; e < NE; e++) {
        int n1 = nt[e] * NX1;
        for (int i = tid; i < n1; i += 256)
            g_items[b1[e] + i] = (e << 11) | ((i >> 6) << 6) | (i & 63);
        int n2 = nt[e] * NX2;
        for (int i = tid; i < n2; i += 256)
            g_items[b2[e] + i] = (1 << 14) | (e << 11) | ((i >> 4) << 6) | (i & 15);
    }
}

// ---------------- persistent fused MoE GEMM kernel ----------------------------
// Phase 0 (GEMM1): H[e,rows,xcols] = silu(X@w1)*(X@w3), BM=128, 64 logical cols
//   (n' = 128 interleaved: 8 w1 + matching 8 w3 per 16), K=HDIM, fp32 weights
//   converted in-loader. Signals g_done[e,mt] when its x-item completes.
// Phase 1 (GEMM2): out[tok] += w * (H@w2) tile, BM=128, BN=64, K=IDIM.
//   Waits for all NX1 phase-0 items of (e,mt). Exactly 2 atomic adds per output
//   element onto 0.0 -> bitwise deterministic (IEEE add is commutative).
__global__ __launch_bounds__(256, 2) void moe_kernel(
    const __half* __restrict__ Xg, const float* __restrict__ W1,
    const float* __restrict__ W3, const float* __restrict__ W2,
    __half* __restrict__ Hb, float* __restrict__ out) {

    __shared__ __half As_[2][128 * 40];   // A tiles, row stride 40 halves
    __shared__ __half Bs_[2][32 * 136];   // B tiles, row stride 136 halves
    __shared__ int   s_item;
    __shared__ int   s_tok[128];
    __shared__ float s_w[128];

    int tid = threadIdx.x;
    int lane = tid & 31;
    int wid = tid >> 5;
    int wm = (wid & 3) * 32;
    int fr = lane >> 2;
    int fc = (lane & 3) * 2;
    int lrow  = (lane & 7) + ((lane >> 3) & 1) * 8;
    int lcol8 = (lane >> 4) * 8;

    int nitems = g_nitems;

    for (;;) {
        __syncthreads();   // protect smem reuse across items
        if (tid == 0) s_item = atomicAdd(&g_next, 1);
        __syncthreads();
        int it = s_item;
        if (it >= nitems) return;
        int v = g_items[it];
        int e = (v >> 11) & 7, mt = (v >> 6) & 31, x = v & 63;
        int cnt = g_cnt[e];
        int row0 = mt << 7;

        if (!(v & (1 << 14))) {
            // ---------------- phase 0: GEMM1 (fused silu) ----------------
            const __half* Ab = Xg + (size_t)(e * CAP + row0) * HDIM;
            const float* Wp1 = W1 + (size_t)e * HDIM * IDIM + x * 64;
            const float* Wp3 = W3 + (size_t)e * HDIM * IDIM + x * 64;
            int wn = (wid >> 2) * 64;

            float acc[2][8][4];
            #pragma unroll
            for (int mi = 0; mi < 2; mi++)
                #pragma unroll
                for (int ni = 0; ni < 8; ni++)
                    #pragma unroll
                    for (int j = 0; j < 4; j++) acc[mi][ni][j] = 0.f;

            float4 stage[4];
            auto ldgB = [&](int kt) {
                #pragma unroll
                for (int l = 0; l < 2; l++) {
                    int q = tid + l * 256, k = q >> 4, c4 = q & 15;
                    stage[l]     = *(const float4*)(Wp1 + (size_t)(kt + k) * IDIM + c4 * 4);
                    stage[l + 2] = *(const float4*)(Wp3 + (size_t)(kt + k) * IDIM + c4 * 4);
                }
            };
            auto stsB = [&](int buf) {
                __half* B = Bs_[buf];
                #pragma unroll
                for (int l = 0; l < 2; l++) {
                    int q = tid + l * 256, k = q >> 4, c4 = q & 15;
                    int n = (c4 >> 1) * 16 + (c4 & 1) * 4;
                    float4 vv = stage[l];
                    __half2 h0 = __floats2half2_rn(vv.x, vv.y);
                    __half2 h1 = __floats2half2_rn(vv.z, vv.w);
                    uint2 u; u.x = *(unsigned*)&h0; u.y = *(unsigned*)&h1;
                    *(uint2*)(B + k * 136 + n) = u;
                    vv = stage[l + 2];
                    h0 = __floats2half2_rn(vv.x, vv.y);
                    h1 = __floats2half2_rn(vv.z, vv.w);
                    u.x = *(unsigned*)&h0; u.y = *(unsigned*)&h1;
                    *(uint2*)(B + k * 136 + n + 8) = u;
                }
            };
            auto ldA = [&](int kt, int buf) {
                unsigned sa = smem_u32(As_[buf]);
                const char* Asrc = (const char*)(Ab + kt);
                #pragma unroll
                for (int l = 0; l < 2; l++) {
                    int q = tid + l * 256, row = q >> 2, c = q & 3;
                    CPA16(sa + (unsigned)(row * 80 + c * 16),
                          Asrc + (size_t)row * HDIM * 2 + c * 16);
                }
            };

            ldgB(0); ldA(0, 0); CP_COMMIT();
            const int NK = HDIM >> 5;
            for (int i = 0; i < NK; i++) {
                int buf = i & 1;
                stsB(buf);
                if (i + 1 < NK) ldgB((i + 1) * 32);
                asm volatile("cp.async.wait_group 0;");
                __syncthreads();
                if (i + 1 < NK) { ldA((i + 1) * 32, buf ^ 1); CP_COMMIT(); }

                unsigned aBase = smem_u32(As_[buf]) + (unsigned)(((wm + lrow) * 40 + lcol8) * 2);
                unsigned bBase = smem_u32(Bs_[buf]) + (unsigned)(lrow * 272 + (wn + lcol8) * 2);
                #pragma unroll
                for (int ks = 0; ks < 32; ks += 16) {
                    unsigned a[2][4], b[8][2];
                    LDSM4(a[0], aBase + ks * 2);
                    LDSM4(a[1], aBase + 16 * 80 + ks * 2);
                    #pragma unroll
                    for (int p = 0; p < 4; p++)
                        LDSM4T(b[2 * p][0], b[2 * p][1], b[2 * p + 1][0], b[2 * p + 1][1],
                               bBase + ks * 272 + p * 32);
                    #pragma unroll
                    for (int mi = 0; mi < 2; mi++)
                        #pragma unroll
                        for (int ni = 0; ni < 8; ni++)
                            MMA16816(acc[mi][ni], a[mi], b[ni]);
                }
                __syncthreads();
            }

            // epilogue: silu(t1)*t3 -> H
            #pragma unroll
            for (int mi = 0; mi < 2; mi++) {
                int r = wm + mi * 16 + fr;
                __half* Crow0 = Hb + (size_t)(e * CAP + row0 + r) * IDIM + x * 64;
                __half* Crow1 = Crow0 + (size_t)8 * IDIM;
                #pragma unroll
                for (int ng = 0; ng < 4; ng++) {
                    int col = (wn >> 4) * 8 + ng * 8 + fc;
                    float t10 = acc[mi][2 * ng][0],     t11 = acc[mi][2 * ng][1];
                    float t30 = acc[mi][2 * ng + 1][0], t31 = acc[mi][2 * ng + 1][1];
                    float h0 = t10 / (1.f + expf(-t10)) * t30;
                    float h1 = t11 / (1.f + expf(-t11)) * t31;
                    *(__half2*)(Crow0 + col) = __floats2half2_rn(h0, h1);
                    t10 = acc[mi][2 * ng][2];     t11 = acc[mi][2 * ng][3];
                    t30 = acc[mi][2 * ng + 1][2]; t31 = acc[mi][2 * ng + 1][3];
                    h0 = t10 / (1.f + expf(-t10)) * t30;
                    h1 = t11 / (1.f + expf(-t11)) * t31;
                    *(__half2*)(Crow1 + col) = __floats2half2_rn(h0, h1);
                }
            }
            __threadfence();
            __syncthreads();
            if (tid == 0) atomicAdd(&g_done[(e << 5) | mt], 1);
        } else {
            // ---------------- phase 1: GEMM2 + atomic combine ----------------
            if (tid == 0) {
                while (atomicAdd(&g_done[(e << 5) | mt], 0) < NX1) __nanosleep(128);
            }
            __syncthreads();
            __threadfence();

            if (tid < 128) {
                int r = row0 + tid;
                if (r < cnt) {
                    s_tok[tid] = g_tok[e * CAP + r];
                    s_w[tid]   = g_w[e * CAP + r];
                } else s_tok[tid] = -1;
            }

            const __half* Ab = Hb + (size_t)(e * CAP + row0) * IDIM;
            const float* Wp = W2 + (size_t)e * IDIM * HDIM + x * 64;
            int wn = (wid >> 2) * 32;

            float acc[2][4][4];
            #pragma unroll
            for (int mi = 0; mi < 2; mi++)
                #pragma unroll
                for (int ni = 0; ni < 4; ni++)
                    #pragma unroll
                    for (int j = 0; j < 4; j++) acc[mi][ni][j] = 0.f;

            float4 stage[2];
            auto ldgB = [&](int kt) {
                #pragma unroll
                for (int l = 0; l < 2; l++) {
                    int q = tid + l * 256, k = q >> 4, c4 = q & 15;
                    stage[l] = *(const float4*)(Wp + (size_t)(kt + k) * HDIM + c4 * 4);
                }
            };
            auto stsB = [&](int buf) {
                __half* B = Bs_[buf];
                #pragma unroll
                for (int l = 0; l < 2; l++) {
                    int q = tid + l * 256, k = q >> 4, c4 = q & 15;
                    float4 vv = stage[l];
                    __half2 h0 = __floats2half2_rn(vv.x, vv.y);
                    __half2 h1 = __floats2half2_rn(vv.z, vv.w);
                    uint2 u; u.x = *(unsigned*)&h0; u.y = *(unsigned*)&h1;
                    *(uint2*)(B + k * 136 + c4 * 4) = u;
                }
            };
            auto ldA = [&](int kt, int buf) {
                unsigned sa = smem_u32(As_[buf]);
                const char* Asrc = (const char*)(Ab + kt);
                #pragma unroll
                for (int l = 0; l < 2; l++) {
                    int q = tid + l * 256, row = q >> 2, c = q & 3;
                    CPA16(sa + (unsigned)(row * 80 + c * 16),
                          Asrc + (size_t)row * IDIM * 2 + c * 16);
                }
            };

            ldgB(0); ldA(0, 0); CP_COMMIT();
            const int NK = IDIM >> 5;
            for (int i = 0; i < NK; i++) {
                int buf = i & 1;
                stsB(buf);
                if (i + 1 < NK) ldgB((i + 1) * 32);
                asm volatile("cp.async.wait_group 0;");
                __syncthreads();
                if (i + 1 < NK) { ldA((i + 1) * 32, buf ^ 1); CP_COMMIT(); }

                unsigned aBase = smem_u32(As_[buf]) + (unsigned)(((wm + lrow) * 40 + lcol8) * 2);
                unsigned bBase = smem_u32(Bs_[buf]) + (unsigned)(lrow * 272 + (wn + lcol8) * 2);
                #pragma unroll
                for (int ks = 0; ks < 32; ks += 16) {
                    unsigned a[2][4], b[4][2];
                    LDSM4(a[0], aBase + ks * 2);
                    LDSM4(a[1], aBase + 16 * 80 + ks * 2);
                    #pragma unroll
                    for (int p = 0; p < 2; p++)
                        LDSM4T(b[2 * p][0], b[2 * p][1], b[2 * p + 1][0], b[2 * p + 1][1],
                               bBase + ks * 272 + p * 32);
                    #pragma unroll
                    for (int mi = 0; mi < 2; mi++)
                        #pragma unroll
                        for (int ni = 0; ni < 4; ni++)
                            MMA16816(acc[mi][ni], a[mi], b[ni]);
                }
                __syncthreads();
            }

            // epilogue: out[tok] += w * acc   (2 adds/element total -> deterministic)
            #pragma unroll
            for (int mi = 0; mi < 2; mi++) {
                int r = wm + mi * 16 + fr;
                #pragma unroll
                for (int half = 0; half < 2; half++) {
                    int rr = r + half * 8;
                    int tok = s_tok[rr];
                    if (tok >= 0) {
                        float wgt = s_w[rr];
                        float* orow = out + (size_t)tok * HDIM + x * 64;
                        #pragma unroll
                        for (int ni = 0; ni < 4; ni++) {
                            int col = wn + ni * 8 + fc;
                            atomicAdd(orow + col,     wgt * acc[mi][ni][2 * half]);
                            atomicAdd(orow + col + 1, wgt * acc[mi][ni][2 * half + 1]);
                        }
                    }
                }
            }
        }
    }
}

// ---------------- launcher ----------------------------------------------------
extern "C" void kernel_launch(void* const* d_in, const int* in_sizes, int n_in,
                              void* d_out, int out_size) {
    const float* X  = (const float*)d_in[0];   // [2,2048,1024]
    const float* GW = (const float*)d_in[1];   // [1024,8]
    const float* W1 = (const float*)d_in[2];   // [8,1024,4096]
    const float* W3 = (const float*)d_in[3];   // [8,1024,4096]
    const float* W2 = (const float*)d_in[4];   // [8,4096,1024]
    float* out = (float*)d_out;
    float* out_logits = out + (size_t)NTOK * HDIM;

    __half* xg;  cudaGetSymbolAddress((void**)&xg, g_Xg);
    __half* hh;  cudaGetSymbolAddress((void**)&hh, g_H);

    zero_kernel<<<1, 256>>>();
    router_kernel<<<NTOK, 256>>>(X, GW, out, out_logits);
    gather_kernel<<<NASSIGN, 256>>>(X);
    build_items_kernel<<<1, 256>>>();
    moe_kernel<<<NCTA, 256>>>(xg, W1, W3, W2, hh, out);
}

// round 11
// speedup vs baseline: 1.0983x; 1.0983x over previous
#include <cuda_runtime.h>
#include <cuda_fp16.h>
#include <math.h>
#include <stdint.h>

#define NE    8
#define HDIM  1024
#define IDIM  4096
#define NTOK  4096
#define CAP   4096
#define NASSIGN (NTOK * 2)

// ---------------- scratch (static device globals) ----------------------------
__device__ __half g_Xg[NE * CAP * HDIM];   // gathered activations fp16
__device__ __half g_H [NE * CAP * IDIM];   // silu(X@w1)*(X@w3) fp16
__device__ int   g_cnt[NE];
__device__ int   g_tok[NE * CAP];          // slot -> token
__device__ float g_w [NE * CAP];           // slot -> combine weight

// ---------------- helpers -----------------------------------------------------
__device__ __forceinline__ unsigned smem_u32(const void* p) {
    return (unsigned)__cvta_generic_to_shared(p);
}
#define CPA16(dst, src) asm volatile("cp.async.cg.shared.global [%0], [%1], 16;" :: "r"(dst), "l"(src))
#define CP_COMMIT()     asm volatile("cp.async.commit_group;")

#define LDSM4(R, addr) \
    asm volatile("ldmatrix.sync.aligned.m8n8.x4.shared.b16 {%0,%1,%2,%3}, [%4];" \
        : "=r"((R)[0]), "=r"((R)[1]), "=r"((R)[2]), "=r"((R)[3]) : "r"(addr))
#define LDSM4T(r0, r1, r2, r3, addr) \
    asm volatile("ldmatrix.sync.aligned.m8n8.x4.trans.shared.b16 {%0,%1,%2,%3}, [%4];" \
        : "=r"(r0), "=r"(r1), "=r"(r2), "=r"(r3) : "r"(addr))
#define MMA16816(acc, a, b) \
    asm volatile("mma.sync.aligned.m16n8k16.row.col.f32.f16.f16.f32 " \
        "{%0,%1,%2,%3}, {%4,%5,%6,%7}, {%8,%9}, {%0,%1,%2,%3};" \
        : "+f"((acc)[0]), "+f"((acc)[1]), "+f"((acc)[2]), "+f"((acc)[3]) \
        : "r"((a)[0]), "r"((a)[1]), "r"((a)[2]), "r"((a)[3]), "r"((b)[0]), "r"((b)[1]))

// ---------------- kernel 0: zero counters ------------------------------------
__global__ void zero_kernel() {
    if (threadIdx.x < NE) g_cnt[threadIdx.x] = 0;
}

// ---------------- kernel 1: router + scatter + gather + out-zero --------------
__global__ void router_kernel(const float* __restrict__ X,
                              const float* __restrict__ GW,
                              float* __restrict__ out,
                              float* __restrict__ out_logits) {
    int t = blockIdx.x;
    int w = threadIdx.x >> 5;
    int lane = threadIdx.x & 31;
    __shared__ float slog[NE];
    __shared__ int ss0, ss1;

    const float* x = X + (size_t)t * HDIM;
    int i = threadIdx.x;
    float4 v = ((const float4*)x)[i];      // this thread's 4 elements (reused below)

    float acc = 0.f;
    for (int j = lane; j < HDIM; j += 32)
        acc += x[j] * GW[j * NE + w];
    #pragma unroll
    for (int o = 16; o > 0; o >>= 1)
        acc += __shfl_xor_sync(0xffffffffu, acc, o);
    if (lane == 0) {
        slog[w] = acc;
        out_logits[t * NE + w] = acc;
    }

    // zero this token's output row (poisoned by harness)
    ((float4*)(out + (size_t)t * HDIM))[i] = make_float4(0.f, 0.f, 0.f, 0.f);

    __syncthreads();
    if (threadIdx.x == 0) {
        int i0 = 0; float l0 = slog[0];
        #pragma unroll
        for (int e = 1; e < NE; e++)
            if (slog[e] > l0) { l0 = slog[e]; i0 = e; }
        int i1 = -1; float l1 = -1e30f;
        #pragma unroll
        for (int e = 0; e < NE; e++)
            if (e != i0 && slog[e] > l1) { l1 = slog[e]; i1 = e; }
        float e1 = expf(l1 - l0);
        float inv = 1.f / (1.f + e1);
        int p0 = atomicAdd(&g_cnt[i0], 1);
        int s0 = i0 * CAP + p0;
        g_tok[s0] = t; g_w[s0] = inv;  ss0 = s0;
        int p1 = atomicAdd(&g_cnt[i1], 1);
        int s1 = i1 * CAP + p1;
        g_tok[s1] = t; g_w[s1] = e1 * inv;  ss1 = s1;
    }
    __syncthreads();

    // gather: convert this token's row to fp16 into both expert slots
    __half2 h0 = __floats2half2_rn(v.x, v.y);
    __half2 h1 = __floats2half2_rn(v.z, v.w);
    __half2* d0 = (__half2*)(g_Xg + (size_t)ss0 * HDIM);
    __half2* d1 = (__half2*)(g_Xg + (size_t)ss1 * HDIM);
    d0[2 * i] = h0; d0[2 * i + 1] = h1;
    d1[2 * i] = h0; d1[2 * i + 1] = h1;
}

// ---------------- GEMM (mma.sync + ldmatrix, direct fp32 weights) ------------
// A [rows][K] fp16 K-contig (g_Xg or g_H). Weights fp32, [K][n] n-contiguous.
// BM=128, BN=128, BK=32. 8 warps: 4 along M, 2 along N.
// FUSE=1: n' interleave (8 w1-cols + matching 8 w3-cols per 16) -> thread ni
//         even/odd = (t1,t3) same logical col; writes silu(t1)*t3 fp16 to H.
// FUSE=0: GEMM2; epilogue does weighted atomicAdd combine into fp32 out.
template <int FUSE>
__global__ __launch_bounds__(256, 2) void gemm_f16_kernel(
    const __half* __restrict__ A, const float* __restrict__ Wa,
    const float* __restrict__ Wb, __half* __restrict__ C,
    float* __restrict__ out, int K) {

    int e  = blockIdx.y >> 5;
    int mt = blockIdx.y & 31;
    int cnt = g_cnt[e];
    int row0 = mt * 128;
    if (row0 >= cnt) return;

    __shared__ __half As_[2][128 * 40];   // row stride 40 halves (80B)
    __shared__ __half Bs_[2][32 * 136];   // row stride 136 halves (272B)
    __shared__ int   s_tok[128];
    __shared__ float s_w[128];

    const __half* Ab = A + (size_t)(e * CAP + row0) * K;
    const float* Wp1;
    const float* Wp3 = nullptr;
    if (FUSE) {
        Wp1 = Wa + (size_t)e * HDIM * IDIM + blockIdx.x * 64;
        Wp3 = Wb + (size_t)e * HDIM * IDIM + blockIdx.x * 64;
    } else {
        Wp1 = Wa + (size_t)e * IDIM * HDIM + blockIdx.x * 128;
    }

    int tid = threadIdx.x;
    int lane = tid & 31;
    int wid = tid >> 5;
    int wm = (wid & 3) * 32;
    int wn = (wid >> 2) * 64;
    int fr = lane >> 2;
    int fc = (lane & 3) * 2;
    int lrow  = (lane & 7) + ((lane >> 3) & 1) * 8;
    int lcol8 = (lane >> 4) * 8;

    if (!FUSE && tid < 128) {
        int r = row0 + tid;
        if (r < cnt) {
            s_tok[tid] = g_tok[e * CAP + r];
            s_w[tid]   = g_w[e * CAP + r];
        } else s_tok[tid] = -1;
    }

    float acc[2][8][4];
    #pragma unroll
    for (int mi = 0; mi < 2; mi++)
        #pragma unroll
        for (int ni = 0; ni < 8; ni++)
            #pragma unroll
            for (int j = 0; j < 4; j++) acc[mi][ni][j] = 0.f;

    float4 stage[4];

    auto ldgB = [&](int kt) {
        if (FUSE) {
            #pragma unroll
            for (int l = 0; l < 2; l++) {
                int q = tid + l * 256, k = q >> 4, c4 = q & 15;
                stage[l]     = *(const float4*)(Wp1 + (size_t)(kt + k) * IDIM + c4 * 4);
                stage[l + 2] = *(const float4*)(Wp3 + (size_t)(kt + k) * IDIM + c4 * 4);
            }
        } else {
            #pragma unroll
            for (int l = 0; l < 4; l++) {
                int q = tid + l * 256, k = q >> 5, c4 = q & 31;
                stage[l] = *(const float4*)(Wp1 + (size_t)(kt + k) * HDIM + c4 * 4);
            }
        }
    };
    auto stsB = [&](int buf) {
        __half* B = Bs_[buf];
        if (FUSE) {
            #pragma unroll
            for (int l = 0; l < 2; l++) {
                int q = tid + l * 256, k = q >> 4, c4 = q & 15;
                int n = (c4 >> 1) * 16 + (c4 & 1) * 4;
                float4 vv = stage[l];
                __half2 h0 = __floats2half2_rn(vv.x, vv.y);
                __half2 h1 = __floats2half2_rn(vv.z, vv.w);
                uint2 u; u.x = *(unsigned*)&h0; u.y = *(unsigned*)&h1;
                *(uint2*)(B + k * 136 + n) = u;
                vv = stage[l + 2];
                h0 = __floats2half2_rn(vv.x, vv.y);
                h1 = __floats2half2_rn(vv.z, vv.w);
                u.x = *(unsigned*)&h0; u.y = *(unsigned*)&h1;
                *(uint2*)(B + k * 136 + n + 8) = u;
            }
        } else {
            #pragma unroll
            for (int l = 0; l < 4; l++) {
                int q = tid + l * 256, k = q >> 5, c4 = q & 31;
                float4 vv = stage[l];
                __half2 h0 = __floats2half2_rn(vv.x, vv.y);
                __half2 h1 = __floats2half2_rn(vv.z, vv.w);
                uint2 u; u.x = *(unsigned*)&h0; u.y = *(unsigned*)&h1;
                *(uint2*)(B + k * 136 + c4 * 4) = u;
            }
        }
    };
    auto ldA = [&](int kt, int buf) {
        unsigned sa = smem_u32(As_[buf]);
        const char* Asrc = (const char*)(Ab + kt);
        #pragma unroll
        for (int l = 0; l < 2; l++) {
            int q = tid + l * 256, row = q >> 2, c = q & 3;
            CPA16(sa + (unsigned)(row * 80 + c * 16), Asrc + (size_t)row * K * 2 + c * 16);
        }
    };

    ldgB(0);
    ldA(0, 0);
    CP_COMMIT();

    int NK = K >> 5;
    for (int i = 0; i < NK; i++) {
        int buf = i & 1;
        stsB(buf);
        if (i + 1 < NK) ldgB((i + 1) * 32);
        asm volatile("cp.async.wait_group 0;");
        __syncthreads();
        if (i + 1 < NK) { ldA((i + 1) * 32, buf ^ 1); CP_COMMIT(); }

        unsigned aBase = smem_u32(As_[buf]) + (unsigned)(((wm + lrow) * 40 + lcol8) * 2);
        unsigned bBase = smem_u32(Bs_[buf]) + (unsigned)(lrow * 272 + (wn + lcol8) * 2);

        #pragma unroll
        for (int ks = 0; ks < 32; ks += 16) {
            unsigned a[2][4], b[8][2];
            LDSM4(a[0], aBase + ks * 2);
            LDSM4(a[1], aBase + 16 * 80 + ks * 2);
            #pragma unroll
            for (int p = 0; p < 4; p++)
                LDSM4T(b[2 * p][0], b[2 * p][1], b[2 * p + 1][0], b[2 * p + 1][1],
                       bBase + ks * 272 + p * 32);
            #pragma unroll
            for (int mi = 0; mi < 2; mi++)
                #pragma unroll
                for (int ni = 0; ni < 8; ni++)
                    MMA16816(acc[mi][ni], a[mi], b[ni]);
        }
        __syncthreads();
    }

    // epilogue
    if (FUSE) {
        #pragma unroll
        for (int mi = 0; mi < 2; mi++) {
            int r = wm + mi * 16 + fr;
            __half* Crow0 = C + (size_t)(e * CAP + row0 + r) * IDIM + blockIdx.x * 64;
            __half* Crow1 = Crow0 + (size_t)8 * IDIM;
            #pragma unroll
            for (int ng = 0; ng < 4; ng++) {
                int col = (wn >> 4) * 8 + ng * 8 + fc;
                float t10 = acc[mi][2 * ng][0],     t11 = acc[mi][2 * ng][1];
                float t30 = acc[mi][2 * ng + 1][0], t31 = acc[mi][2 * ng + 1][1];
                float h0 = t10 / (1.f + expf(-t10)) * t30;
                float h1 = t11 / (1.f + expf(-t11)) * t31;
                *(__half2*)(Crow0 + col) = __floats2half2_rn(h0, h1);
                t10 = acc[mi][2 * ng][2];     t11 = acc[mi][2 * ng][3];
                t30 = acc[mi][2 * ng + 1][2]; t31 = acc[mi][2 * ng + 1][3];
                h0 = t10 / (1.f + expf(-t10)) * t30;
                h1 = t11 / (1.f + expf(-t11)) * t31;
                *(__half2*)(Crow1 + col) = __floats2half2_rn(h0, h1);
            }
        }
    } else {
        // weighted combine: out[tok] += w * acc (2 adds/element total)
        #pragma unroll
        for (int mi = 0; mi < 2; mi++) {
            int r = wm + mi * 16 + fr;
            #pragma unroll
            for (int half = 0; half < 2; half++) {
                int rr = r + half * 8;
                int tok = s_tok[rr];
                if (tok >= 0) {
                    float wgt = s_w[rr];
                    float* orow = out + (size_t)tok * HDIM + blockIdx.x * 128;
                    #pragma unroll
                    for (int ni = 0; ni < 8; ni++) {
                        int col = wn + ni * 8 + fc;
                        atomicAdd(orow + col,     wgt * acc[mi][ni][2 * half]);
                        atomicAdd(orow + col + 1, wgt * acc[mi][ni][2 * half + 1]);
                    }
                }
            }
        }
    }
}

// ---------------- launcher ----------------------------------------------------
extern "C" void kernel_launch(void* const* d_in, const int* in_sizes, int n_in,
                              void* d_out, int out_size) {
    const float* X  = (const float*)d_in[0];   // [2,2048,1024]
    const float* GW = (const float*)d_in[1];   // [1024,8]
    const float* W1 = (const float*)d_in[2];   // [8,1024,4096]
    const float* W3 = (const float*)d_in[3];   // [8,1024,4096]
    const float* W2 = (const float*)d_in[4];   // [8,4096,1024]
    float* out = (float*)d_out;
    float* out_logits = out + (size_t)NTOK * HDIM;

    __half* xg;  cudaGetSymbolAddress((void**)&xg, g_Xg);
    __half* hh;  cudaGetSymbolAddress((void**)&hh, g_H);

    zero_kernel<<<1, 32>>>();
    router_kernel<<<NTOK, 256>>>(X, GW, out, out_logits);

    // H = silu(X@w1) * (X@w3)   (fused, fp32 weights consumed directly)
    gemm_f16_kernel<1><<<dim3(IDIM / 64, NE * 32), 256>>>(xg, W1, W3, hh, nullptr, HDIM);
    // out += combine-weighted H @ w2   (fused epilogue combine)
    gemm_f16_kernel<0><<<dim3(HDIM / 128, NE * 32), 256>>>(hh, W2, nullptr, nullptr, out, IDIM);
}

// round 15
// speedup vs baseline: 1.1429x; 1.0406x over previous
#include <cuda_runtime.h>
#include <cuda_fp16.h>
#include <math.h>
#include <stdint.h>

#define NE    8
#define HDIM  1024
#define IDIM  4096
#define NTOK  4096
#define CAP   4096
#define NASSIGN (NTOK * 2)

// ---------------- scratch (static device globals) ----------------------------
__device__ __half g_Xg[NE * CAP * HDIM];   // gathered activations fp16
__device__ __half g_H [NE * CAP * IDIM];   // silu(X@w1)*(X@w3) fp16
__device__ __half g_Y [NE * CAP * HDIM];   // expert outputs fp16
__device__ int   g_cnt[NE];
__device__ int   g_slotOf[NASSIGN];        // assignment -> slot
__device__ float g_w [NE * CAP];           // slot -> combine weight

// ---------------- helpers -----------------------------------------------------
__device__ __forceinline__ unsigned smem_u32(const void* p) {
    return (unsigned)__cvta_generic_to_shared(p);
}
#define CPA16(dst, src) asm volatile("cp.async.cg.shared.global [%0], [%1], 16;" :: "r"(dst), "l"(src))
#define CP_COMMIT()     asm volatile("cp.async.commit_group;")

#define LDSM4(R, addr) \
    asm volatile("ldmatrix.sync.aligned.m8n8.x4.shared.b16 {%0,%1,%2,%3}, [%4];" \
        : "=r"((R)[0]), "=r"((R)[1]), "=r"((R)[2]), "=r"((R)[3]) : "r"(addr))
#define LDSM4T(r0, r1, r2, r3, addr) \
    asm volatile("ldmatrix.sync.aligned.m8n8.x4.trans.shared.b16 {%0,%1,%2,%3}, [%4];" \
        : "=r"(r0), "=r"(r1), "=r"(r2), "=r"(r3) : "r"(addr))
#define MMA16816(acc, a, b) \
    asm volatile("mma.sync.aligned.m16n8k16.row.col.f32.f16.f16.f32 " \
        "{%0,%1,%2,%3}, {%4,%5,%6,%7}, {%8,%9}, {%0,%1,%2,%3};" \
        : "+f"((acc)[0]), "+f"((acc)[1]), "+f"((acc)[2]), "+f"((acc)[3]) \
        : "r"((a)[0]), "r"((a)[1]), "r"((a)[2]), "r"((a)[3]), "r"((b)[0]), "r"((b)[1]))

// ---------------- kernel 0: zero counters ------------------------------------
__global__ void zero_kernel() {
    if (threadIdx.x < NE) g_cnt[threadIdx.x] = 0;
}

// ---------------- kernel 1: router + scatter + gather ------------------------
__global__ void router_kernel(const float* __restrict__ X,
                              const float* __restrict__ GW,
                              float* __restrict__ out_logits) {
    int t = blockIdx.x;
    int w = threadIdx.x >> 5;
    int lane = threadIdx.x & 31;
    __shared__ float slog[NE];
    __shared__ int ss0, ss1;

    const float* x = X + (size_t)t * HDIM;
    int i = threadIdx.x;
    float4 v = ((const float4*)x)[i];      // this thread's 4 elements (reused below)

    float acc = 0.f;
    for (int j = lane; j < HDIM; j += 32)
        acc += x[j] * GW[j * NE + w];
    #pragma unroll
    for (int o = 16; o > 0; o >>= 1)
        acc += __shfl_xor_sync(0xffffffffu, acc, o);
    if (lane == 0) {
        slog[w] = acc;
        out_logits[t * NE + w] = acc;
    }
    __syncthreads();

    if (threadIdx.x == 0) {
        int i0 = 0; float l0 = slog[0];
        #pragma unroll
        for (int e = 1; e < NE; e++)
            if (slog[e] > l0) { l0 = slog[e]; i0 = e; }
        int i1 = -1; float l1 = -1e30f;
        #pragma unroll
        for (int e = 0; e < NE; e++)
            if (e != i0 && slog[e] > l1) { l1 = slog[e]; i1 = e; }
        float e1 = expf(l1 - l0);
        float inv = 1.f / (1.f + e1);
        int p0 = atomicAdd(&g_cnt[i0], 1);
        int s0 = i0 * CAP + p0;
        g_slotOf[2 * t] = s0; g_w[s0] = inv;        ss0 = s0;
        int p1 = atomicAdd(&g_cnt[i1], 1);
        int s1 = i1 * CAP + p1;
        g_slotOf[2 * t + 1] = s1; g_w[s1] = e1 * inv; ss1 = s1;
    }
    __syncthreads();

    // gather: convert this token's row to fp16 into both expert slots
    __half2 h0 = __floats2half2_rn(v.x, v.y);
    __half2 h1 = __floats2half2_rn(v.z, v.w);
    __half2* d0 = (__half2*)(g_Xg + (size_t)ss0 * HDIM);
    __half2* d1 = (__half2*)(g_Xg + (size_t)ss1 * HDIM);
    d0[2 * i] = h0; d0[2 * i + 1] = h1;
    d1[2 * i] = h0; d1[2 * i + 1] = h1;
}

// ---------------- GEMM (mma.sync + ldmatrix, direct fp32 weights) ------------
// A [rows][K] fp16 K-contig (g_Xg or g_H). Weights fp32, [K][n] n-contiguous.
// BM=128, BN=128, BK=32. 8 warps: 4 along M, 2 along N.
// ONE __syncthreads per K-tile. Visibility protocol: every thread finishes its
// own cp.async groups (wait_group 0) BEFORE the end-of-iteration barrier, so
// after the barrier all SMEM writes (STS + cp.async) are visible to all.
// FUSE=1: n' interleave (8 w1-cols + matching 8 w3-cols per 16) -> thread ni
//         even/odd = (t1,t3) same logical col; writes silu(t1)*t3 fp16 to H.
// FUSE=0: plain 128-col tile store to C (ld = gridDim.x*128).
template <int FUSE>
__global__ __launch_bounds__(256, 2) void gemm_f16_kernel(
    const __half* __restrict__ A, const float* __restrict__ Wa,
    const float* __restrict__ Wb, __half* __restrict__ C, int K) {

    int e  = blockIdx.y >> 5;
    int mt = blockIdx.y & 31;
    int cnt = g_cnt[e];
    int row0 = mt * 128;
    if (row0 >= cnt) return;

    __shared__ __half As_[2][128 * 40];   // row stride 40 halves (80B)
    __shared__ __half Bs_[2][32 * 136];   // row stride 136 halves (272B)

    const __half* Ab = A + (size_t)(e * CAP + row0) * K;
    const float* Wp1;
    const float* Wp3 = nullptr;
    if (FUSE) {
        Wp1 = Wa + (size_t)e * HDIM * IDIM + blockIdx.x * 64;
        Wp3 = Wb + (size_t)e * HDIM * IDIM + blockIdx.x * 64;
    } else {
        Wp1 = Wa + (size_t)e * IDIM * HDIM + blockIdx.x * 128;
    }

    int tid = threadIdx.x;
    int lane = tid & 31;
    int wid = tid >> 5;
    int wm = (wid & 3) * 32;
    int wn = (wid >> 2) * 64;
    int fr = lane >> 2;
    int fc = (lane & 3) * 2;
    int lrow  = (lane & 7) + ((lane >> 3) & 1) * 8;
    int lcol8 = (lane >> 4) * 8;

    float acc[2][8][4];
    #pragma unroll
    for (int mi = 0; mi < 2; mi++)
        #pragma unroll
        for (int ni = 0; ni < 8; ni++)
            #pragma unroll
            for (int j = 0; j < 4; j++) acc[mi][ni][j] = 0.f;

    float4 stage[4];

    // ti = K-tile index; element offset = ti*32
    auto ldgB = [&](int ti) {
        int kt = ti * 32;
        if (FUSE) {
            #pragma unroll
            for (int l = 0; l < 2; l++) {
                int q = tid + l * 256, k = q >> 4, c4 = q & 15;
                stage[l]     = *(const float4*)(Wp1 + (size_t)(kt + k) * IDIM + c4 * 4);
                stage[l + 2] = *(const float4*)(Wp3 + (size_t)(kt + k) * IDIM + c4 * 4);
            }
        } else {
            #pragma unroll
            for (int l = 0; l < 4; l++) {
                int q = tid + l * 256, k = q >> 5, c4 = q & 31;
                stage[l] = *(const float4*)(Wp1 + (size_t)(kt + k) * HDIM + c4 * 4);
            }
        }
    };
    auto stsB = [&](int buf) {
        __half* B = Bs_[buf];
        if (FUSE) {
            #pragma unroll
            for (int l = 0; l < 2; l++) {
                int q = tid + l * 256, k = q >> 4, c4 = q & 15;
                int n = (c4 >> 1) * 16 + (c4 & 1) * 4;
                float4 vv = stage[l];
                __half2 h0 = __floats2half2_rn(vv.x, vv.y);
                __half2 h1 = __floats2half2_rn(vv.z, vv.w);
                uint2 u; u.x = *(unsigned*)&h0; u.y = *(unsigned*)&h1;
                *(uint2*)(B + k * 136 + n) = u;
                vv = stage[l + 2];
                h0 = __floats2half2_rn(vv.x, vv.y);
                h1 = __floats2half2_rn(vv.z, vv.w);
                u.x = *(unsigned*)&h0; u.y = *(unsigned*)&h1;
                *(uint2*)(B + k * 136 + n + 8) = u;
            }
        } else {
            #pragma unroll
            for (int l = 0; l < 4; l++) {
                int q = tid + l * 256, k = q >> 5, c4 = q & 31;
                float4 vv = stage[l];
                __half2 h0 = __floats2half2_rn(vv.x, vv.y);
                __half2 h1 = __floats2half2_rn(vv.z, vv.w);
                uint2 u; u.x = *(unsigned*)&h0; u.y = *(unsigned*)&h1;
                *(uint2*)(B + k * 136 + c4 * 4) = u;
            }
        }
    };
    auto ldA = [&](int ti, int buf) {
        unsigned sa = smem_u32(As_[buf]);
        const char* Asrc = (const char*)(Ab + ti * 32);
        #pragma unroll
        for (int l = 0; l < 2; l++) {
            int q = tid + l * 256, row = q >> 2, c = q & 3;
            CPA16(sa + (unsigned)(row * 80 + c * 16), Asrc + (size_t)row * K * 2 + c * 16);
        }
    };

    int NK = K >> 5;

    // prologue: B(0) staged+stored, B(1) staged, A(0) copied and WAITED,
    // then one barrier -> everything for tile 0 visible to all threads.
    ldgB(0);
    stsB(0);
    ldgB(1);
    ldA(0, 0); CP_COMMIT();
    asm volatile("cp.async.wait_group 0;");
    __syncthreads();

    for (int i = 0; i < NK; i++) {
        int buf = i & 1;
        if (i + 1 < NK) { ldA(i + 1, buf ^ 1); CP_COMMIT(); }

        unsigned aBase = smem_u32(As_[buf]) + (unsigned)(((wm + lrow) * 40 + lcol8) * 2);
        unsigned bBase = smem_u32(Bs_[buf]) + (unsigned)(lrow * 272 + (wn + lcol8) * 2);

        #pragma unroll
        for (int ks = 0; ks < 32; ks += 16) {
            unsigned a[2][4], b[8][2];
            LDSM4(a[0], aBase + ks * 2);
            LDSM4(a[1], aBase + 16 * 80 + ks * 2);
            #pragma unroll
            for (int p = 0; p < 4; p++)
                LDSM4T(b[2 * p][0], b[2 * p][1], b[2 * p + 1][0], b[2 * p + 1][1],
                       bBase + ks * 272 + p * 32);
            #pragma unroll
            for (int mi = 0; mi < 2; mi++)
                #pragma unroll
                for (int ni = 0; ni < 8; ni++)
                    MMA16816(acc[mi][ni], a[mi], b[ni]);
        }

        if (i + 1 < NK) {
            stsB(buf ^ 1);                 // B(i+1) -> alternate buffer
            if (i + 2 < NK) ldgB(i + 2);   // stage B(i+2)
            asm volatile("cp.async.wait_group 0;");   // own A(i+1) done
        }
        __syncthreads();   // all writes for tile i+1 now visible to all
    }

    // epilogue
    if (FUSE) {
        #pragma unroll
        for (int mi = 0; mi < 2; mi++) {
            int r = wm + mi * 16 + fr;
            __half* Crow0 = C + (size_t)(e * CAP + row0 + r) * IDIM + blockIdx.x * 64;
            __half* Crow1 = Crow0 + (size_t)8 * IDIM;
            #pragma unroll
            for (int ng = 0; ng < 4; ng++) {
                int col = (wn >> 4) * 8 + ng * 8 + fc;
                float t10 = acc[mi][2 * ng][0],     t11 = acc[mi][2 * ng][1];
                float t30 = acc[mi][2 * ng + 1][0], t31 = acc[mi][2 * ng + 1][1];
                float h0 = t10 / (1.f + expf(-t10)) * t30;
                float h1 = t11 / (1.f + expf(-t11)) * t31;
                *(__half2*)(Crow0 + col) = __floats2half2_rn(h0, h1);
                t10 = acc[mi][2 * ng][2];     t11 = acc[mi][2 * ng][3];
                t30 = acc[mi][2 * ng + 1][2]; t31 = acc[mi][2 * ng + 1][3];
                h0 = t10 / (1.f + expf(-t10)) * t30;
                h1 = t11 / (1.f + expf(-t11)) * t31;
                *(__half2*)(Crow1 + col) = __floats2half2_rn(h0, h1);
            }
        }
    } else {
        int Ntot = gridDim.x * 128;
        #pragma unroll
        for (int mi = 0; mi < 2; mi++) {
            int r = wm + mi * 16 + fr;
            __half* Crow0 = C + (size_t)(e * CAP + row0 + r) * Ntot + blockIdx.x * 128;
            __half* Crow1 = Crow0 + (size_t)8 * Ntot;
            #pragma unroll
            for (int ni = 0; ni < 8; ni++) {
                int col = wn + ni * 8 + fc;
                *(__half2*)(Crow0 + col) = __floats2half2_rn(acc[mi][ni][0], acc[mi][ni][1]);
                *(__half2*)(Crow1 + col) = __floats2half2_rn(acc[mi][ni][2], acc[mi][ni][3]);
            }
        }
    }
}

// ---------------- kernel: weighted combine -----------------------------------
__global__ void combine_kernel(float* __restrict__ out) {
    int t = blockIdx.x;
    int s0 = g_slotOf[2 * t], s1 = g_slotOf[2 * t + 1];
    float w0 = g_w[s0], w1 = g_w[s1];
    const __half2* y0 = (const __half2*)(g_Y + (size_t)s0 * HDIM);
    const __half2* y1 = (const __half2*)(g_Y + (size_t)s1 * HDIM);
    float2* orow = (float2*)(out + (size_t)t * HDIM);
    #pragma unroll
    for (int j = threadIdx.x; j < HDIM / 2; j += 256) {
        float2 a = __half22float2(y0[j]);
        float2 b = __half22float2(y1[j]);
        float2 r;
        r.x = w0 * a.x + w1 * b.x;
        r.y = w0 * a.y + w1 * b.y;
        orow[j] = r;
    }
}

// ---------------- launcher ----------------------------------------------------
extern "C" void kernel_launch(void* const* d_in, const int* in_sizes, int n_in,
                              void* d_out, int out_size) {
    const float* X  = (const float*)d_in[0];   // [2,2048,1024]
    const float* GW = (const float*)d_in[1];   // [1024,8]
    const float* W1 = (const float*)d_in[2];   // [8,1024,4096]
    const float* W3 = (const float*)d_in[3];   // [8,1024,4096]
    const float* W2 = (const float*)d_in[4];   // [8,4096,1024]
    float* out = (float*)d_out;
    float* out_logits = out + (size_t)NTOK * HDIM;

    __half* xg;  cudaGetSymbolAddress((void**)&xg, g_Xg);
    __half* hh;  cudaGetSymbolAddress((void**)&hh, g_H);
    __half* yy;  cudaGetSymbolAddress((void**)&yy, g_Y);

    zero_kernel<<<1, 32>>>();
    router_kernel<<<NTOK, 256>>>(X, GW, out_logits);

    // H = silu(X@w1) * (X@w3)   (fused, fp32 weights consumed directly)
    gemm_f16_kernel<1><<<dim3(IDIM / 64, NE * 32), 256>>>(xg, W1, W3, hh, HDIM);
    // Y = H @ w2
    gemm_f16_kernel<0><<<dim3(HDIM / 128, NE * 32), 256>>>(hh, W2, nullptr, yy, IDIM);

    combine_kernel<<<NTOK, 256>>>(out);
}